// round 1
// baseline (speedup 1.0000x reference)
#include <cuda_runtime.h>

// Problem constants
#define BATCH 32
#define CH    256
#define HH    56
#define WW    56
#define HW    3136      // 56*56
#define KK2   2304      // CH*9
#define MEXP  8

// Scratch (device globals: no allocation allowed in kernel_launch)
__device__ float g_gap[BATCH * CH];
__device__ float g_alpha[BATCH * MEXP];
__device__ float g_biasc[BATCH * CH];
__device__ float g_wT[(size_t)BATCH * KK2 * CH];   // [b][k][o], k-major combined weights (75.5 MB)

// ---------------------------------------------------------------------------
// 1) Global average pool: g_gap[b*CH+c] = mean(x[b,c,:,:])
// ---------------------------------------------------------------------------
__global__ void gap_kernel(const float* __restrict__ x) {
    int bc = blockIdx.x;                       // b*CH + c
    const float* p = x + (size_t)bc * HW;
    float s = 0.f;
    for (int i = threadIdx.x; i < HW; i += 128) s += p[i];
    __shared__ float sm[4];
    #pragma unroll
    for (int off = 16; off; off >>= 1) s += __shfl_down_sync(0xffffffffu, s, off);
    if ((threadIdx.x & 31) == 0) sm[threadIdx.x >> 5] = s;
    __syncthreads();
    if (threadIdx.x == 0)
        g_gap[bc] = (sm[0] + sm[1] + sm[2] + sm[3]) * (1.f / (float)HW);
}

// ---------------------------------------------------------------------------
// 2) Gate: logits = gap @ gate_w^T + gate_b ; alpha = softmax ; biasc = alpha @ bias
//    Single block, 256 threads.
// ---------------------------------------------------------------------------
__global__ void gate_kernel(const float* __restrict__ gate_w,
                            const float* __restrict__ gate_b,
                            const float* __restrict__ bias) {
    __shared__ float lg[BATCH][MEXP];
    __shared__ float al[BATCH][MEXP];
    int t = threadIdx.x;
    int b = t >> 3, m = t & 7;                 // 32 x 8 = 256
    float acc = gate_b[m];
    const float* gp = &g_gap[b * CH];
    const float* gw = &gate_w[m * CH];
    for (int i = 0; i < CH; i++) acc += gp[i] * gw[i];
    lg[b][m] = acc;
    __syncthreads();
    if (t < BATCH) {
        float mx = lg[t][0];
        #pragma unroll
        for (int j = 1; j < MEXP; j++) mx = fmaxf(mx, lg[t][j]);
        float e[MEXP], s = 0.f;
        #pragma unroll
        for (int j = 0; j < MEXP; j++) { e[j] = expf(lg[t][j] - mx); s += e[j]; }
        float inv = 1.f / s;
        #pragma unroll
        for (int j = 0; j < MEXP; j++) { al[t][j] = e[j] * inv; g_alpha[t * MEXP + j] = e[j] * inv; }
    }
    __syncthreads();
    // combined bias: biasc[b][o] = sum_m alpha[b][m] * bias[m][o]; thread t = channel o
    for (int b2 = 0; b2 < BATCH; b2++) {
        float s = 0.f;
        #pragma unroll
        for (int j = 0; j < MEXP; j++) s += al[b2][j] * bias[j * CH + t];
        g_biasc[b2 * CH + t] = s;
    }
}

// ---------------------------------------------------------------------------
// 3) Combine experts + transpose to k-major:
//    g_wT[b][k][o] = sum_m alpha[b][m] * weight[m][o][k]   (k = c*9 + kh*3 + kw)
//    32x32 (o x k) smem-tile transpose: coalesced reads AND coalesced writes.
//    grid (72, 8, 32) = (k-tiles, o-tiles, b), 256 threads.
// ---------------------------------------------------------------------------
__global__ void combine_kernel(const float* __restrict__ weight) {
    int b  = blockIdx.z;
    int o0 = blockIdx.y * 32;
    int k0 = blockIdx.x * 32;
    __shared__ float tbuf[32][33];
    float a[MEXP];
    #pragma unroll
    for (int m = 0; m < MEXP; m++) a[m] = g_alpha[b * MEXP + m];

    int i  = threadIdx.x >> 3;           // o within tile, 0..31
    int j4 = (threadIdx.x & 7) * 4;      // k within tile, step 4
    float4 acc = make_float4(0.f, 0.f, 0.f, 0.f);
    #pragma unroll
    for (int m = 0; m < MEXP; m++) {
        const float4 v = *(const float4*)(weight + ((size_t)m * CH + (o0 + i)) * KK2 + k0 + j4);
        acc.x += a[m] * v.x; acc.y += a[m] * v.y; acc.z += a[m] * v.z; acc.w += a[m] * v.w;
    }
    tbuf[i][j4 + 0] = acc.x; tbuf[i][j4 + 1] = acc.y;
    tbuf[i][j4 + 2] = acc.z; tbuf[i][j4 + 3] = acc.w;
    __syncthreads();

    int jo  = threadIdx.x >> 3;          // k row 0..31
    int io4 = (threadIdx.x & 7) * 4;     // o, step 4
    float4 wv = make_float4(tbuf[io4 + 0][jo], tbuf[io4 + 1][jo],
                            tbuf[io4 + 2][jo], tbuf[io4 + 3][jo]);
    *(float4*)(&g_wT[((size_t)b * KK2 + k0 + jo) * CH + o0 + io4]) = wv;
}

// ---------------------------------------------------------------------------
// 4) Implicit-im2col GEMM per sample:
//    out[b][o][p] = biasc[b][o] + sum_k wT[b][k][o] * im2col(x_b)[k][p]
//    Tiles: BM=128 (o), BN=128 (pixels), BK=16. 256 threads, 8x8 microtile.
//    grid (25, 2, 32) = (pixel-tiles, o-tiles, b).
// ---------------------------------------------------------------------------
#define BM  128
#define BN  128
#define BKC 16

__global__ void __launch_bounds__(256, 2)
conv_kernel(const float* __restrict__ x, float* __restrict__ out) {
    int b  = blockIdx.z;
    int o0 = blockIdx.y * BM;
    int p0 = blockIdx.x * BN;
    __shared__ float Xs[BKC][BN];
    __shared__ float Ws[BKC][BM];
    int tid = threadIdx.x;
    int lk  = tid >> 4;            // load row 0..15
    int lp  = (tid & 15) * 8;      // load col base

    // Precompute (h,w,valid) for this thread's 8 im2col pixels (fixed per CTA)
    int ph[8], pw[8];
    bool pv[8];
    #pragma unroll
    for (int j = 0; j < 8; j++) {
        int p = p0 + lp + j;
        pv[j] = p < HW;
        int pp = pv[j] ? p : 0;
        ph[j] = pp / WW;
        pw[j] = pp - ph[j] * WW;
    }

    int orow = tid >> 4;           // 0..15 -> 8 o's each
    int pcol = tid & 15;           // 0..15 -> 8 pixels each
    float acc[8][8];
    #pragma unroll
    for (int i = 0; i < 8; i++) {
        float bi = g_biasc[b * CH + o0 + orow * 8 + i];
        #pragma unroll
        for (int j = 0; j < 8; j++) acc[i][j] = bi;
    }

    const float* xb = x + (size_t)b * CH * HW;
    const float* wb = g_wT + (size_t)b * KK2 * CH;

    for (int k0 = 0; k0 < KK2; k0 += BKC) {
        // --- load W tile (coalesced, k-major scratch) ---
        {
            const float* wr = wb + (size_t)(k0 + lk) * CH + o0 + lp;
            *(float4*)&Ws[lk][lp]     = *(const float4*)(wr);
            *(float4*)&Ws[lk][lp + 4] = *(const float4*)(wr + 4);
        }
        // --- load X tile (implicit im2col, bounds-checked) ---
        {
            int k   = k0 + lk;
            int c   = k / 9;
            int rem = k - c * 9;
            int kh  = rem / 3;
            int kw  = rem - kh * 3;
            const float* xc = xb + (size_t)c * HW;
            float v[8];
            #pragma unroll
            for (int j = 0; j < 8; j++) {
                int ih = ph[j] + kh - 1;
                int iw = pw[j] + kw - 1;
                bool ok = pv[j] && ((unsigned)ih < HH) && ((unsigned)iw < WW);
                v[j] = ok ? xc[ih * WW + iw] : 0.f;
            }
            *(float4*)&Xs[lk][lp]     = make_float4(v[0], v[1], v[2], v[3]);
            *(float4*)&Xs[lk][lp + 4] = make_float4(v[4], v[5], v[6], v[7]);
        }
        __syncthreads();
        #pragma unroll
        for (int kk = 0; kk < BKC; kk++) {
            float wr[8], xr[8];
            *(float4*)&wr[0] = *(float4*)&Ws[kk][orow * 8];
            *(float4*)&wr[4] = *(float4*)&Ws[kk][orow * 8 + 4];
            *(float4*)&xr[0] = *(float4*)&Xs[kk][pcol * 8];
            *(float4*)&xr[4] = *(float4*)&Xs[kk][pcol * 8 + 4];
            #pragma unroll
            for (int i = 0; i < 8; i++)
                #pragma unroll
                for (int j = 0; j < 8; j++)
                    acc[i][j] += wr[i] * xr[j];
        }
        __syncthreads();
    }

    // --- store (NCHW) ---
    #pragma unroll
    for (int i = 0; i < 8; i++) {
        int o = o0 + orow * 8 + i;
        float* op = out + ((size_t)b * CH + o) * HW;
        #pragma unroll
        for (int j = 0; j < 8; j++) {
            int p = p0 + pcol * 8 + j;
            if (p < HW) op[p] = acc[i][j];
        }
    }
}

// ---------------------------------------------------------------------------
extern "C" void kernel_launch(void* const* d_in, const int* in_sizes, int n_in,
                              void* d_out, int out_size) {
    const float* x      = (const float*)d_in[0];  // (32,256,56,56)
    const float* weight = (const float*)d_in[1];  // (8,256,256,3,3)
    const float* bias   = (const float*)d_in[2];  // (8,256)
    const float* gate_w = (const float*)d_in[3];  // (8,256)
    const float* gate_b = (const float*)d_in[4];  // (8,)
    float* out = (float*)d_out;                   // (32,256,56,56) fp32

    gap_kernel<<<BATCH * CH, 128>>>(x);
    gate_kernel<<<1, 256>>>(gate_w, gate_b, bias);
    combine_kernel<<<dim3(KK2 / 32, CH / 32, BATCH), 256>>>(weight);
    conv_kernel<<<dim3((HW + BN - 1) / BN, CH / BM, BATCH), 256>>>(x, out);
}

// round 4
// speedup vs baseline: 2.2350x; 2.2350x over previous
#include <cuda_runtime.h>
#include <cstdint>

#define BATCH 32
#define CH    256
#define HH    56
#define WW    56
#define HW    3136
#define KK2   2304      // CH*9
#define MEXP  8

#define BM 128          // o per CTA
#define BN 128          // pixels per CTA
#define BK 32           // k per chunk
#define NCHUNK (KK2 / BK)   // 72

// smem: rows padded 64B data + 16B = 80B stride (conflict-free ldmatrix: 80*r mod 128 hits all 8 banks)
#define ROWB   80
#define TILE_B (128 * ROWB)                 // 10240 per tile
#define OFF_AH0 0
#define OFF_AL0 (OFF_AH0 + TILE_B)
#define OFF_BH0 (OFF_AL0 + TILE_B)
#define OFF_BL0 (OFF_BH0 + TILE_B)
#define STAGE   (4 * TILE_B)                // 40960
#define SMEM_BYTES (2 * STAGE)              // 81920

// Scratch
__device__ float g_gap[BATCH * CH];
__device__ float g_alpha[BATCH * MEXP];
__device__ float g_biasc[BATCH * CH];
__device__ float g_wc[(size_t)BATCH * CH * KK2];   // combined weights [b][o][k]

// ---------------- helpers ----------------
__device__ __forceinline__ uint32_t smem_u32(const void* p) {
    uint32_t a;
    asm("{ .reg .u64 t; cvta.to.shared.u64 t, %1; cvt.u32.u64 %0, t; }" : "=r"(a) : "l"(p));
    return a;
}
__device__ __forceinline__ void split2(float x0, float x1, uint32_t& h, uint32_t& l) {
    // h = {bf16(x1) : bf16(x0)}  (x0 in low half = smaller k)
    asm("cvt.rn.bf16x2.f32 %0, %1, %2;" : "=r"(h) : "f"(x1), "f"(x0));
    float r0 = x0 - __uint_as_float(h << 16);
    float r1 = x1 - __uint_as_float(h & 0xffff0000u);
    asm("cvt.rn.bf16x2.f32 %0, %1, %2;" : "=r"(l) : "f"(r1), "f"(r0));
}
__device__ __forceinline__ void ldsm4(uint32_t& r0, uint32_t& r1, uint32_t& r2, uint32_t& r3,
                                      uint32_t addr) {
    asm volatile("ldmatrix.sync.aligned.m8n8.x4.shared.b16 {%0,%1,%2,%3}, [%4];"
                 : "=r"(r0), "=r"(r1), "=r"(r2), "=r"(r3) : "r"(addr));
}
__device__ __forceinline__ void mma16816(float* c, const uint32_t* a, uint32_t b0, uint32_t b1) {
    asm volatile(
        "mma.sync.aligned.m16n8k16.row.col.f32.bf16.bf16.f32 "
        "{%0,%1,%2,%3}, {%4,%5,%6,%7}, {%8,%9}, {%0,%1,%2,%3};"
        : "+f"(c[0]), "+f"(c[1]), "+f"(c[2]), "+f"(c[3])
        : "r"(a[0]), "r"(a[1]), "r"(a[2]), "r"(a[3]), "r"(b0), "r"(b1));
}

// ---------------------------------------------------------------------------
// 1) Global average pool
// ---------------------------------------------------------------------------
__global__ void gap_kernel(const float* __restrict__ x) {
    int bc = blockIdx.x;
    const float* p = x + (size_t)bc * HW;
    float s = 0.f;
    for (int i = threadIdx.x; i < HW; i += 128) s += p[i];
    __shared__ float sm[4];
    #pragma unroll
    for (int off = 16; off; off >>= 1) s += __shfl_down_sync(0xffffffffu, s, off);
    if ((threadIdx.x & 31) == 0) sm[threadIdx.x >> 5] = s;
    __syncthreads();
    if (threadIdx.x == 0)
        g_gap[bc] = (sm[0] + sm[1] + sm[2] + sm[3]) * (1.f / (float)HW);
}

// ---------------------------------------------------------------------------
// 2) Gate softmax + combined bias
// ---------------------------------------------------------------------------
__global__ void gate_kernel(const float* __restrict__ gate_w,
                            const float* __restrict__ gate_b,
                            const float* __restrict__ bias) {
    __shared__ float lg[BATCH][MEXP];
    __shared__ float al[BATCH][MEXP];
    int t = threadIdx.x;
    int b = t >> 3, m = t & 7;
    float acc = gate_b[m];
    const float* gp = &g_gap[b * CH];
    const float* gw = &gate_w[m * CH];
    for (int i = 0; i < CH; i++) acc += gp[i] * gw[i];
    lg[b][m] = acc;
    __syncthreads();
    if (t < BATCH) {
        float mx = lg[t][0];
        #pragma unroll
        for (int j = 1; j < MEXP; j++) mx = fmaxf(mx, lg[t][j]);
        float e[MEXP], s = 0.f;
        #pragma unroll
        for (int j = 0; j < MEXP; j++) { e[j] = expf(lg[t][j] - mx); s += e[j]; }
        float inv = 1.f / s;
        #pragma unroll
        for (int j = 0; j < MEXP; j++) { al[t][j] = e[j] * inv; g_alpha[t * MEXP + j] = e[j] * inv; }
    }
    __syncthreads();
    for (int b2 = 0; b2 < BATCH; b2++) {
        float s = 0.f;
        #pragma unroll
        for (int j = 0; j < MEXP; j++) s += al[b2][j] * bias[j * CH + t];
        g_biasc[b2 * CH + t] = s;
    }
}

// ---------------------------------------------------------------------------
// 3) Combine experts: g_wc[b][o][k] = sum_m alpha[b][m] * weight[m][o][k]
// ---------------------------------------------------------------------------
__global__ void combine_kernel(const float* __restrict__ weight) {
    int b = blockIdx.y;
    size_t i4 = (size_t)blockIdx.x * 256 + threadIdx.x;
    float a[MEXP];
    #pragma unroll
    for (int m = 0; m < MEXP; m++) a[m] = g_alpha[b * MEXP + m];
    float4 acc = make_float4(0.f, 0.f, 0.f, 0.f);
    #pragma unroll
    for (int m = 0; m < MEXP; m++) {
        const float4 v = ((const float4*)(weight + (size_t)m * CH * KK2))[i4];
        acc.x += a[m] * v.x; acc.y += a[m] * v.y;
        acc.z += a[m] * v.z; acc.w += a[m] * v.w;
    }
    ((float4*)(g_wc + (size_t)b * CH * KK2))[i4] = acc;
}

// ---------------------------------------------------------------------------
// 4) Conv = per-sample implicit-im2col GEMM with mma.sync bf16 (bf16x3 split)
//    grid (25, 2, 32), 256 threads, 8 warps in 4(m) x 2(n).
// ---------------------------------------------------------------------------
__global__ void __launch_bounds__(256, 1)
conv_mma_kernel(const float* __restrict__ x, float* __restrict__ out) {
    extern __shared__ char smem[];
    const uint32_t sbase = smem_u32(smem);
    const int tid  = threadIdx.x;
    const int wid  = tid >> 5;
    const int lane = tid & 31;
    const int warp_m = wid >> 1;           // 0..3 -> m offset *32
    const int warp_n = wid & 1;            // 0..1 -> n offset *64

    const int b  = blockIdx.z;
    const int o0 = blockIdx.y * BM;
    const int p0 = blockIdx.x * BN;

    // -------- producer indices --------
    const int ar  = tid >> 1;              // A: o-row 0..127
    const int seg = tid & 1;               // A: k half (16 floats)
    // B: warp wid owns k = kc + wid*4 .. +3 ; lane+32j = pixel row (j<4)
    int hj[4], wj[4]; bool vj[4];
    #pragma unroll
    for (int j = 0; j < 4; j++) {
        int p = p0 + lane + 32 * j;
        vj[j] = p < HW;
        int pp = vj[j] ? p : 0;
        hj[j] = pp / WW;
        wj[j] = pp - hj[j] * WW;
    }

    const float* xb = x + (size_t)b * CH * HW;
    const float* wbase = g_wc + ((size_t)(b * CH) + o0 + ar) * KK2 + seg * 16;

    // ldmatrix per-lane row offsets (row-pad 80B makes these conflict-free)
    const uint32_t aRow = (uint32_t)(warp_m * 32 + (lane & 15)) * ROWB + ((lane >> 4) * 16);
    const uint32_t bRow = (uint32_t)(warp_n * 64 + (lane & 15)) * ROWB + ((lane >> 4) * 16);

    float acc[2][8][4];
    #pragma unroll
    for (int t = 0; t < 2; t++)
        #pragma unroll
        for (int j = 0; j < 8; j++)
            #pragma unroll
            for (int q = 0; q < 4; q++) acc[t][j][q] = 0.f;

    float va[16], vb[16];

    // ---- stage loaders ----
    auto loadStage = [&](int chunk) {
        const int kc = chunk * BK;
        const float* wr = wbase + kc;
        #pragma unroll
        for (int q = 0; q < 4; q++) {
            float4 v = *(const float4*)(wr + q * 4);
            va[q * 4 + 0] = v.x; va[q * 4 + 1] = v.y;
            va[q * 4 + 2] = v.z; va[q * 4 + 3] = v.w;
        }
        const int kb = kc + wid * 4;
        int cc[4], dh[4], dw[4];
        #pragma unroll
        for (int kk = 0; kk < 4; kk++) {
            int k = kb + kk;
            cc[kk] = k / 9;
            int r = k - cc[kk] * 9;
            int r3 = r / 3;
            dh[kk] = r3 - 1;
            dw[kk] = r - r3 * 3 - 1;
        }
        #pragma unroll
        for (int j = 0; j < 4; j++)
            #pragma unroll
            for (int kk = 0; kk < 4; kk++) {
                int ih = hj[j] + dh[kk];
                int iw = wj[j] + dw[kk];
                bool ok = vj[j] && ((unsigned)ih < HH) && ((unsigned)iw < WW);
                vb[j * 4 + kk] = ok ? xb[(size_t)cc[kk] * HW + ih * WW + iw] : 0.f;
            }
    };
    auto storeStage = [&](int s) {
        char* sb = smem + s * STAGE;
        // A: 16 floats -> 2 x uint4 hi + 2 x uint4 lo
        uint32_t h[8], l[8];
        #pragma unroll
        for (int i = 0; i < 8; i++) split2(va[2 * i], va[2 * i + 1], h[i], l[i]);
        uint32_t aoff = (uint32_t)ar * ROWB + seg * 32;
        *(uint4*)(sb + OFF_AH0 + aoff)      = make_uint4(h[0], h[1], h[2], h[3]);
        *(uint4*)(sb + OFF_AH0 + aoff + 16) = make_uint4(h[4], h[5], h[6], h[7]);
        *(uint4*)(sb + OFF_AL0 + aoff)      = make_uint4(l[0], l[1], l[2], l[3]);
        *(uint4*)(sb + OFF_AL0 + aoff + 16) = make_uint4(l[4], l[5], l[6], l[7]);
        // B: per pixel row: 4 floats -> 2 b32 hi + 2 b32 lo
        #pragma unroll
        for (int j = 0; j < 4; j++) {
            uint32_t bh0, bl0, bh1, bl1;
            split2(vb[j * 4 + 0], vb[j * 4 + 1], bh0, bl0);
            split2(vb[j * 4 + 2], vb[j * 4 + 3], bh1, bl1);
            uint32_t boff = (uint32_t)(lane + 32 * j) * ROWB + wid * 8;
            *(uint2*)(sb + OFF_BH0 + boff) = make_uint2(bh0, bh1);
            *(uint2*)(sb + OFF_BL0 + boff) = make_uint2(bl0, bl1);
        }
    };

    // ---- prologue: chunk 0 ----
    loadStage(0);
    storeStage(0);
    __syncthreads();

    for (int c0 = 0; c0 < NCHUNK; c0++) {
        const int s = c0 & 1;
        const bool more = (c0 + 1 < NCHUNK);
        if (more) loadStage(c0 + 1);

        const uint32_t sAh = sbase + s * STAGE + OFF_AH0 + aRow;
        const uint32_t sAl = sbase + s * STAGE + OFF_AL0 + aRow;
        const uint32_t sBh = sbase + s * STAGE + OFF_BH0 + bRow;
        const uint32_t sBl = sbase + s * STAGE + OFF_BL0 + bRow;

        #pragma unroll
        for (int kk = 0; kk < 2; kk++) {
            uint32_t ah[2][4], al_[2][4], bh[4][4], bl[4][4];
            #pragma unroll
            for (int t = 0; t < 2; t++) {
                ldsm4(ah[t][0], ah[t][1], ah[t][2], ah[t][3], sAh + t * (16 * ROWB) + kk * 32);
                ldsm4(al_[t][0], al_[t][1], al_[t][2], al_[t][3], sAl + t * (16 * ROWB) + kk * 32);
            }
            #pragma unroll
            for (int nb = 0; nb < 4; nb++) {
                ldsm4(bh[nb][0], bh[nb][1], bh[nb][2], bh[nb][3], sBh + nb * (16 * ROWB) + kk * 32);
                ldsm4(bl[nb][0], bl[nb][1], bl[nb][2], bl[nb][3], sBl + nb * (16 * ROWB) + kk * 32);
            }
            #pragma unroll
            for (int t = 0; t < 2; t++)
                #pragma unroll
                for (int nb = 0; nb < 4; nb++) {
                    // j0 = 2nb (frag regs 0,2), j1 = 2nb+1 (frag regs 1,3)
                    mma16816(acc[t][2 * nb],     ah[t],  bh[nb][0], bh[nb][2]);
                    mma16816(acc[t][2 * nb],     ah[t],  bl[nb][0], bl[nb][2]);
                    mma16816(acc[t][2 * nb],     al_[t], bh[nb][0], bh[nb][2]);
                    mma16816(acc[t][2 * nb + 1], ah[t],  bh[nb][1], bh[nb][3]);
                    mma16816(acc[t][2 * nb + 1], ah[t],  bl[nb][1], bl[nb][3]);
                    mma16816(acc[t][2 * nb + 1], al_[t], bh[nb][1], bh[nb][3]);
                }
        }
        if (more) storeStage(s ^ 1);
        __syncthreads();
    }

    // ---- epilogue ----
    #pragma unroll
    for (int t = 0; t < 2; t++) {
        int r0 = o0 + warp_m * 32 + t * 16 + (lane >> 2);
        float bi0 = g_biasc[b * CH + r0];
        float bi1 = g_biasc[b * CH + r0 + 8];
        float* out0 = out + ((size_t)b * CH + r0) * HW;
        float* out1 = out0 + 8 * HW;
        #pragma unroll
        for (int j = 0; j < 8; j++) {
            int p = p0 + warp_n * 64 + j * 8 + (lane & 3) * 2;
            if (p < HW) {
                *(float2*)(out0 + p) = make_float2(acc[t][j][0] + bi0, acc[t][j][1] + bi0);
                *(float2*)(out1 + p) = make_float2(acc[t][j][2] + bi1, acc[t][j][3] + bi1);
            }
        }
    }
}

// ---------------------------------------------------------------------------
extern "C" void kernel_launch(void* const* d_in, const int* in_sizes, int n_in,
                              void* d_out, int out_size) {
    const float* x      = (const float*)d_in[0];
    const float* weight = (const float*)d_in[1];
    const float* bias   = (const float*)d_in[2];
    const float* gate_w = (const float*)d_in[3];
    const float* gate_b = (const float*)d_in[4];
    float* out = (float*)d_out;

    cudaFuncSetAttribute(conv_mma_kernel,
                         cudaFuncAttributeMaxDynamicSharedMemorySize, SMEM_BYTES);

    gap_kernel<<<BATCH * CH, 128>>>(x);
    gate_kernel<<<1, 256>>>(gate_w, gate_b, bias);
    combine_kernel<<<dim3(CH * KK2 / 4 / 256, BATCH), 256>>>(weight);
    conv_mma_kernel<<<dim3((HW + BN - 1) / BN, CH / BM, BATCH), 256, SMEM_BYTES>>>(x, out);
}